// round 11
// baseline (speedup 1.0000x reference)
#include <cuda_runtime.h>
#include <cuda_fp16.h>

#define NN   50000
#define NE   800000
#define EMB  64
#define FIN  32
#define SCALE_F 0.4251202479144762f

#define SCAN_BLK 1024
#define NBLK_SCAN 49            // ceil(50000/1024)

#define CHUNK 64
#define NCHUNK (NE / CHUNK)     // 12500
#define SPMM_BLOCKS 1184        // 148 SMs x 8 resident blocks -> exactly one wave
#define SPMM_WARPS (SPMM_BLOCKS * 8)     // 9472

// ---------------- device scratch (static allocation; no cudaMalloc) ----------------
__device__ float g_cons[NN * EMB];
__device__ float g_var [NN * EMB];
__device__ float4 g_conv4[NN * 16];      // zero-init; re-zeroed by last-flusher after read
__device__ uint2 g_consh[NN * 16];       // half2 shadow of cons (gather operand)
__device__ uint2 g_uh   [NN * 16];       // half2 shadow of u    (gather operand)
__device__ int   g_rowptr[NN + 1];
__device__ int   g_cursor[NN];
__device__ int   g_hist [NN];            // zero at start; scan kernel re-zeroes after reading
__device__ int   g_rcnt [NN];            // zero-init; reset by last flusher each use
__device__ int   g_nexp [NN];            // 64-edge chunks overlapping each row
__device__ int2  g_epack[NE];            // CSR-ordered {dst, w-bits}
__device__ int   g_esrc [NE];            // CSR-ordered src (non-decreasing)
__device__ float g_part[512];
__device__ float g_inv_norm;
__device__ volatile int g_flag[64];      // lookback status: 0=invalid 1=agg 2=prefix
__device__ volatile int g_agg [64];
__device__ volatile int g_pref[64];

// ---------------- launch 0: histogram of src (warp-aggregated) + sumsq partials ----------------
__global__ void k_histsum(const int* __restrict__ ei, const float* __restrict__ ew) {
    int t = threadIdx.x;
    int lane = t & 31;
    if (blockIdx.x == 0 && t < 64) g_flag[t] = 0;
    int stride = gridDim.x * blockDim.x;
    float a = 0.0f;
    for (int e = blockIdx.x * blockDim.x + t; ; e += stride) {
        bool act = (e < NE);
        unsigned m = __ballot_sync(0xFFFFFFFFu, act);
        if (m == 0) break;
        if (act) {
            int s = ei[2 * e];
            unsigned grp = __match_any_sync(m, s);
            int leader = __ffs(grp) - 1;
            if (lane == leader) atomicAdd(&g_hist[s], __popc(grp));
            float w = ew[e];
            a = fmaf(w, w, a);
        }
    }
    __shared__ float red[256];
    red[t] = a;
    __syncthreads();
    for (int off = 128; off > 0; off >>= 1) {
        if (t < off) red[t] += red[t + off];
        __syncthreads();
    }
    if (t == 0) g_part[blockIdx.x] = red[0];
}

// ---------------- launch 1: single-pass decoupled-lookback scan -> rowptr/cursor, inv_norm ----------------
__global__ void __launch_bounds__(SCAN_BLK) k_scan() {
    __shared__ int s[SCAN_BLK];
    __shared__ int s_excl;
    int t = threadIdx.x, bid = blockIdx.x;
    int i = bid * SCAN_BLK + t;
    int val = 0;
    if (i < NN) {
        val = g_hist[i];
        g_hist[i] = 0;                      // restore invariant for next replay
    }
    s[t] = val;
    __syncthreads();
    for (int off = 1; off < SCAN_BLK; off <<= 1) {
        int v = (t >= off) ? s[t - off] : 0;
        __syncthreads();
        s[t] += v;
        __syncthreads();
    }
    int incl = s[t];
    int agg = s[SCAN_BLK - 1];
    if (t == 0) {
        if (bid == 0) {
            g_pref[0] = agg;
            __threadfence();
            g_flag[0] = 2;
            s_excl = 0;
        } else {
            g_agg[bid] = agg;
            __threadfence();
            g_flag[bid] = 1;
            int ex = 0;
            int p = bid - 1;
            while (true) {
                int f;
                while ((f = g_flag[p]) == 0) { }
                if (f == 2) { ex += g_pref[p]; break; }
                ex += g_agg[p];
                p--;
            }
            g_pref[bid] = ex + agg;
            __threadfence();
            g_flag[bid] = 2;
            s_excl = ex;
        }
    }
    __syncthreads();
    int r = incl - val + s_excl;
    if (i < NN) {
        g_rowptr[i] = r;
        g_cursor[i] = r;
    }
    if (bid == NBLK_SCAN - 1) {
        if (t == 0) g_rowptr[NN] = NE;
        __shared__ float fr[256];
        if (t < 256) fr[t] = g_part[t] + g_part[t + 256];
        __syncthreads();
        for (int off = 128; off > 0; off >>= 1) {
            if (t < off) fr[t] += fr[t + off];
            __syncthreads();
        }
        if (t == 0) g_inv_norm = 1.0f / sqrtf(fr[0]);
    }
}

// ---------------- pack 4 floats -> uint2 of half2 ----------------
__device__ __forceinline__ uint2 pack_h4(float a, float b, float c, float d) {
    __half2 lo = __floats2half2_rn(a, b);
    __half2 hi = __floats2half2_rn(c, d);
    uint2 r;
    r.x = *reinterpret_cast<unsigned*>(&lo);
    r.y = *reinterpret_cast<unsigned*>(&hi);
    return r;
}

// ---------------- register-tiled input GEMM: out = relu(x @ W + b), 64 rows/block ----------------
__device__ __forceinline__ void dense_in(const float* __restrict__ x, const float* __restrict__ W,
                                         const float* __restrict__ bias, float* __restrict__ out,
                                         uint2* __restrict__ outh, int row_base) {
    __shared__ float Ws[FIN][EMB];
    __shared__ float xsT[FIN][68];
    __shared__ float bs[EMB];
    int tid = threadIdx.x;
    for (int i = tid; i < FIN * EMB; i += 256) Ws[i >> 6][i & 63] = W[i];
    if (tid < EMB) bs[tid] = bias[tid];
    for (int i = tid; i < 64 * FIN; i += 256) {
        int r = i >> 5, k = i & 31;
        float v = 0.0f;
        if (row_base + r < NN) v = x[(row_base + r) * FIN + k];
        xsT[k][r] = v;
    }
    __syncthreads();
    int tx = tid & 15, ty = tid >> 4;
    int r0 = ty * 4, c0 = tx * 4;
    float acc[4][4];
#pragma unroll
    for (int i = 0; i < 4; i++) {
        acc[i][0] = bs[c0]; acc[i][1] = bs[c0 + 1]; acc[i][2] = bs[c0 + 2]; acc[i][3] = bs[c0 + 3];
    }
#pragma unroll
    for (int k = 0; k < FIN; k++) {
        float4 a = *reinterpret_cast<const float4*>(&xsT[k][r0]);
        float4 bq = *reinterpret_cast<const float4*>(&Ws[k][c0]);
        float av[4] = {a.x, a.y, a.z, a.w};
#pragma unroll
        for (int i = 0; i < 4; i++) {
            acc[i][0] = fmaf(av[i], bq.x, acc[i][0]);
            acc[i][1] = fmaf(av[i], bq.y, acc[i][1]);
            acc[i][2] = fmaf(av[i], bq.z, acc[i][2]);
            acc[i][3] = fmaf(av[i], bq.w, acc[i][3]);
        }
    }
#pragma unroll
    for (int i = 0; i < 4; i++) {
        int row = row_base + r0 + i;
        if (row < NN) {
            float4 o;
            o.x = fmaxf(acc[i][0], 0.0f); o.y = fmaxf(acc[i][1], 0.0f);
            o.z = fmaxf(acc[i][2], 0.0f); o.w = fmaxf(acc[i][3], 0.0f);
            *reinterpret_cast<float4*>(&out[row * EMB + c0]) = o;
            if (outh) outh[row * 16 + tx] = pack_h4(o.x, o.y, o.z, o.w);
        }
    }
}

#define DENSE_BLOCKS 782   // ceil(50000/64)
#define NEXP_BLOCKS 196    // ceil(50000/256)

// ---------------- launch 2: scatter (warp-aggregated) + input GEMMs + nexp precompute ----------------
__global__ void k_scatter_dense(const int* __restrict__ ei, const float* __restrict__ ew,
                                const float* __restrict__ xc, const float* __restrict__ Wc, const float* __restrict__ bc,
                                const float* __restrict__ xv, const float* __restrict__ Wv, const float* __restrict__ bv) {
    if (blockIdx.x < 512) {
        float inv = g_inv_norm;
        int lane = threadIdx.x & 31;
        int stride = 512 * blockDim.x;
        for (int e = blockIdx.x * blockDim.x + threadIdx.x; ; e += stride) {
            bool act = (e < NE);
            unsigned m = __ballot_sync(0xFFFFFFFFu, act);
            if (m == 0) break;
            if (act) {
                int s = ei[2 * e];
                int d = ei[2 * e + 1];
                unsigned grp = __match_any_sync(m, s);
                int leader = __ffs(grp) - 1;
                int rank = __popc(grp & ((1u << lane) - 1));
                int base = 0;
                if (lane == leader) base = atomicAdd(&g_cursor[s], __popc(grp));
                base = __shfl_sync(m, base, leader);
                int slot = base + rank;
                g_epack[slot] = make_int2(d, __float_as_int(ew[e] * inv));
                g_esrc[slot] = s;
            }
        }
    } else if (blockIdx.x < 512 + 2 * DENSE_BLOCKS) {
        int db = blockIdx.x - 512;
        if (db < DENSE_BLOCKS) dense_in(xc, Wc, bc, g_cons, g_consh, db * 64);
        else                   dense_in(xv, Wv, bv, g_var, 0, (db - DENSE_BLOCKS) * 64);
    } else {
        int i = (blockIdx.x - 512 - 2 * DENSE_BLOCKS) * 256 + threadIdx.x;
        if (i < NN) {
            int r0 = g_rowptr[i], r1 = g_rowptr[i + 1];
            g_nexp[i] = (r1 > r0) ? (((r1 - 1) >> 6) - (r0 >> 6) + 1) : 0;   // 64-edge chunks
        }
    }
}

// ---------------- flush: combine halves, 2 atomics/lane, acq_rel counter, fused epilogue ----------------
__device__ __forceinline__ void flush_and_count(int src, float4 acc, int lane, int q16, int h,
                                                const float* __restrict__ rhs,
                                                float t, int mode) {
    acc.x += __shfl_xor_sync(0xFFFFFFFFu, acc.x, 16);
    acc.y += __shfl_xor_sync(0xFFFFFFFFu, acc.y, 16);
    acc.z += __shfl_xor_sync(0xFFFFFFFFu, acc.z, 16);
    acc.w += __shfl_xor_sync(0xFFFFFFFFu, acc.w, 16);
    float* CONV = reinterpret_cast<float*>(g_conv4);
    {   // all 32 lanes: 2 atomics each (lower half takes x/y, upper half z/w)
        int o = src * 64 + q16 * 4 + h * 2;
        atomicAdd(&CONV[o],     h ? acc.z : acc.x);
        atomicAdd(&CONV[o + 1], h ? acc.w : acc.y);
    }
    __syncwarp();                               // orders lanes' conv adds before lane0's release
    int last = 0;
    if (lane == 0) {
        int old;
        asm volatile("atom.acq_rel.gpu.global.add.s32 %0, [%1], %2;"
                     : "=r"(old) : "l"(&g_rcnt[src]), "r"(1) : "memory");
        last = (old + 1 == g_nexp[src]);
    }
    last = __shfl_sync(0xFFFFFFFFu, last, 0);
    if (!last) return;
    __syncwarp();                               // propagate lane0's acquire to all lanes
    if (lane < 16) {
        int i = src * 16 + q16;
        float4 cv = __ldcg(&g_conv4[i]);
        float r = __ldg(&rhs[src]);
        if (mode == 0) {
            float4* V4 = reinterpret_cast<float4*>(g_var);
            float4 vo = V4[i], vn;
            vn.x = fmaxf((vo.x + t * (r - cv.x)) * SCALE_F, 0.0f);
            vn.y = fmaxf((vo.y + t * (r - cv.y)) * SCALE_F, 0.0f);
            vn.z = fmaxf((vo.z + t * (r - cv.z)) * SCALE_F, 0.0f);
            vn.w = fmaxf((vo.w + t * (r - cv.w)) * SCALE_F, 0.0f);
            V4[i] = vn;
            g_uh[i] = pack_h4(2.0f * vn.x - vo.x, 2.0f * vn.y - vo.y,
                              2.0f * vn.z - vo.z, 2.0f * vn.w - vo.w);
        } else {
            float4* C4 = reinterpret_cast<float4*>(g_cons);
            float4 co = C4[i], cn;
            cn.x = fmaxf(co.x - t * (r - cv.x), 0.0f);
            cn.y = fmaxf(co.y - t * (r - cv.y), 0.0f);
            cn.z = fmaxf(co.z - t * (r - cv.z), 0.0f);
            cn.w = fmaxf(co.w - t * (r - cv.w), 0.0f);
            C4[i] = cn;
            g_consh[i] = pack_h4(cn.x, cn.y, cn.z, cn.w);
        }
        g_conv4[i] = make_float4(0.0f, 0.0f, 0.0f, 0.0f);
    }
    __syncwarp();
    if (lane == 0) g_rcnt[src] = 0;
}

// ---------------- fp16 gather accumulate: 4 features per lane ----------------
__device__ __forceinline__ void gacc(const uint2* __restrict__ F16, int d, int q16,
                                     float w, float4& acc) {
    uint2 rv = __ldg(&F16[d * 16 + q16]);
    __half2 h0 = *reinterpret_cast<__half2*>(&rv.x);
    __half2 h1 = *reinterpret_cast<__half2*>(&rv.y);
    float2 f0 = __half22float2(h0);
    float2 f1 = __half22float2(h1);
    acc.x = fmaf(w, f0.x, acc.x);
    acc.y = fmaf(w, f0.y, acc.y);
    acc.z = fmaf(w, f1.x, acc.z);
    acc.w = fmaf(w, f1.y, acc.w);
}

// ---------------- fused SpMM + update: persistent single-wave grid ----------------
// Phase 1: each warp grid-strides over 64-edge chunks (R8 datapath, 32 regs).
// Phase 2: whole grid block-strides the deg-0 elementwise region (disjoint rows -> no race).
__global__ void __launch_bounds__(256) k_spmm_upd(const float* __restrict__ rhs,
                                                  const float* __restrict__ temps,
                                                  int toff, int mode) {
    int tid = threadIdx.x;
    float t = __ldg(&temps[toff]);
    const uint2* __restrict__ F16 = mode ? g_uh : g_consh;
    int lane = tid & 31;
    int h = lane >> 4;          // half 0: even edge of pair, half 1: odd
    int q16 = lane & 15;
    int gwarp = blockIdx.x * 8 + (tid >> 5);

    for (int chunk = gwarp; chunk < NCHUNK; chunk += SPMM_WARPS) {
        int base = chunk * CHUNK;

        // stage 64 edges in registers (coalesced)
        int2 p0 = g_epack[base + lane];
        int2 p1 = g_epack[base + 32 + lane];
        int  s0 = g_esrc [base + lane];
        int  s1 = g_esrc [base + 32 + lane];

        float4 acc = make_float4(0.0f, 0.0f, 0.0f, 0.0f);
        int cur = __shfl_sync(0xFFFFFFFFu, s0, 0);

        // ---- half A (edges 0..31 of chunk) ----
        int lastA = __shfl_sync(0xFFFFFFFFu, s0, 31);
        if (cur == lastA) {
#pragma unroll
            for (int j = 0; j < 32; j += 2) {
                int   d = __shfl_sync(0xFFFFFFFFu, p0.x, j + h);
                float w = __int_as_float(__shfl_sync(0xFFFFFFFFu, p0.y, j + h));
                gacc(F16, d, q16, w, acc);
            }
        } else {
            for (int j = 0; j < 32; j++) {
                int sj = __shfl_sync(0xFFFFFFFFu, s0, j);
                if (sj != cur) { flush_and_count(cur, acc, lane, q16, h, rhs, t, mode);
                                 acc = make_float4(0.0f, 0.0f, 0.0f, 0.0f); cur = sj; }
                int   d = __shfl_sync(0xFFFFFFFFu, p0.x, j);
                float w = __int_as_float(__shfl_sync(0xFFFFFFFFu, p0.y, j));
                if (h == 0) gacc(F16, d, q16, w, acc);
            }
        }

        // ---- half B (edges 32..63 of chunk) ----
        int firstB = __shfl_sync(0xFFFFFFFFu, s1, 0);
        int lastB  = __shfl_sync(0xFFFFFFFFu, s1, 31);
        if (firstB != cur) { flush_and_count(cur, acc, lane, q16, h, rhs, t, mode);
                             acc = make_float4(0.0f, 0.0f, 0.0f, 0.0f); cur = firstB; }
        if (firstB == lastB) {
#pragma unroll
            for (int j = 0; j < 32; j += 2) {
                int   d = __shfl_sync(0xFFFFFFFFu, p1.x, j + h);
                float w = __int_as_float(__shfl_sync(0xFFFFFFFFu, p1.y, j + h));
                gacc(F16, d, q16, w, acc);
            }
        } else {
            for (int j = 0; j < 32; j++) {
                int sj = __shfl_sync(0xFFFFFFFFu, s1, j);
                if (sj != cur) { flush_and_count(cur, acc, lane, q16, h, rhs, t, mode);
                                 acc = make_float4(0.0f, 0.0f, 0.0f, 0.0f); cur = sj; }
                int   d = __shfl_sync(0xFFFFFFFFu, p1.x, j);
                float w = __int_as_float(__shfl_sync(0xFFFFFFFFu, p1.y, j));
                if (h == 0) gacc(F16, d, q16, w, acc);
            }
        }
        flush_and_count(cur, acc, lane, q16, h, rhs, t, mode);
    }

    // grid-stride elementwise update for degree-0 rows (conv == 0)
    int stride = SPMM_BLOCKS * 256;
    for (int i = blockIdx.x * 256 + tid; i < NN * 16; i += stride) {
        int row = i >> 4;
        if (g_nexp[row] != 0) continue;
        float r = __ldg(&rhs[row]);
        if (mode == 0) {
            float4* V = reinterpret_cast<float4*>(g_var);
            float4 vo = V[i], vn;
            float add = t * r;
            vn.x = fmaxf((vo.x + add) * SCALE_F, 0.0f);
            vn.y = fmaxf((vo.y + add) * SCALE_F, 0.0f);
            vn.z = fmaxf((vo.z + add) * SCALE_F, 0.0f);
            vn.w = fmaxf((vo.w + add) * SCALE_F, 0.0f);
            V[i] = vn;
            g_uh[i] = pack_h4(2.0f * vn.x - vo.x, 2.0f * vn.y - vo.y,
                              2.0f * vn.z - vo.z, 2.0f * vn.w - vo.w);
        } else {
            float4* C = reinterpret_cast<float4*>(g_cons);
            float4 co = C[i], cn;
            float sub = t * r;
            cn.x = fmaxf(co.x - sub, 0.0f);
            cn.y = fmaxf(co.y - sub, 0.0f);
            cn.z = fmaxf(co.z - sub, 0.0f);
            cn.w = fmaxf(co.w - sub, 0.0f);
            C[i] = cn;
            g_consh[i] = pack_h4(cn.x, cn.y, cn.z, cn.w);
        }
    }
}

// ---------------- output heads (both in one launch): out = relu(x @ W1 + b1) @ W2 ----------------
__global__ void k_out(const float* __restrict__ W1a, const float* __restrict__ b1a, const float* __restrict__ W2a,
                      const float* __restrict__ W1b, const float* __restrict__ b1b, const float* __restrict__ W2b,
                      float* __restrict__ outbuf) {
    int which = (blockIdx.x >= DENSE_BLOCKS);
    const float* x  = which ? g_cons : g_var;
    const float* W1 = which ? W1b : W1a;
    const float* b1 = which ? b1b : b1a;
    const float* W2 = which ? W2b : W2a;
    float* out = outbuf + which * NN;
    int row_base = (blockIdx.x - which * DENSE_BLOCKS) * 64;

    __shared__ float W1s[EMB][EMB];
    __shared__ float xsT[EMB][68];
    __shared__ float b1s[EMB];
    __shared__ float W2s[EMB];
    int tid = threadIdx.x;
    for (int i = tid; i < EMB * EMB; i += 256) W1s[i >> 6][i & 63] = W1[i];
    if (tid < EMB) { b1s[tid] = b1[tid]; W2s[tid] = W2[tid]; }
    for (int i = tid; i < 64 * EMB; i += 256) {
        int r = i >> 6, k = i & 63;
        float v = 0.0f;
        if (row_base + r < NN) v = x[(row_base + r) * EMB + k];
        xsT[k][r] = v;
    }
    __syncthreads();
    int tx = tid & 15, ty = tid >> 4;
    int r0 = ty * 4, c0 = tx * 4;
    float acc[4][4];
#pragma unroll
    for (int i = 0; i < 4; i++) {
        acc[i][0] = b1s[c0]; acc[i][1] = b1s[c0 + 1]; acc[i][2] = b1s[c0 + 2]; acc[i][3] = b1s[c0 + 3];
    }
#pragma unroll
    for (int k = 0; k < EMB; k++) {
        float4 a = *reinterpret_cast<const float4*>(&xsT[k][r0]);
        float4 bq = *reinterpret_cast<const float4*>(&W1s[k][c0]);
        float av[4] = {a.x, a.y, a.z, a.w};
#pragma unroll
        for (int i = 0; i < 4; i++) {
            acc[i][0] = fmaf(av[i], bq.x, acc[i][0]);
            acc[i][1] = fmaf(av[i], bq.y, acc[i][1]);
            acc[i][2] = fmaf(av[i], bq.z, acc[i][2]);
            acc[i][3] = fmaf(av[i], bq.w, acc[i][3]);
        }
    }
    float4 w2 = *reinterpret_cast<const float4*>(&W2s[c0]);
#pragma unroll
    for (int i = 0; i < 4; i++) {
        float p = fmaxf(acc[i][0], 0.0f) * w2.x + fmaxf(acc[i][1], 0.0f) * w2.y
                + fmaxf(acc[i][2], 0.0f) * w2.z + fmaxf(acc[i][3], 0.0f) * w2.w;
        p += __shfl_down_sync(0xFFFFFFFFu, p, 8, 16);
        p += __shfl_down_sync(0xFFFFFFFFu, p, 4, 16);
        p += __shfl_down_sync(0xFFFFFFFFu, p, 2, 16);
        p += __shfl_down_sync(0xFFFFFFFFu, p, 1, 16);
        int row = row_base + r0 + i;
        if (tx == 0 && row < NN) out[row] = p;
    }
}

// ---------------- launch ----------------
extern "C" void kernel_launch(void* const* d_in, const int* in_sizes, int n_in,
                              void* d_out, int out_size) {
    const float* con_feat   = (const float*)d_in[0];
    const float* var_feat   = (const float*)d_in[1];
    const float* edge_w     = (const float*)d_in[2];
    const float* c          = (const float*)d_in[3];
    const float* b          = (const float*)d_in[4];
    const float* W_cons     = (const float*)d_in[5];
    const float* b_cons     = (const float*)d_in[6];
    const float* W_var      = (const float*)d_in[7];
    const float* b_var      = (const float*)d_in[8];
    const float* temps_ctov = (const float*)d_in[9];
    const float* temps_vtoc = (const float*)d_in[10];
    const float* W1_o1      = (const float*)d_in[11];
    const float* b1_o1      = (const float*)d_in[12];
    const float* W2_o1      = (const float*)d_in[13];
    const float* W1_o2      = (const float*)d_in[14];
    const float* b1_o2      = (const float*)d_in[15];
    const float* W2_o2      = (const float*)d_in[16];
    const int*   edge_index = (const int*)d_in[17];
    float* out = (float*)d_out;

    k_histsum<<<512, 256>>>(edge_index, edge_w);                             // launch 0
    k_scan   <<<NBLK_SCAN, SCAN_BLK>>>();                                    // launch 1
    k_scatter_dense<<<512 + 2 * DENSE_BLOCKS + NEXP_BLOCKS, 256>>>(          // launch 2
        edge_index, edge_w, con_feat, W_cons, b_cons, var_feat, W_var, b_var);

    for (int l = 0; l < 4; l++) {
        k_spmm_upd<<<SPMM_BLOCKS, 256>>>(c, temps_ctov, l * 2 + 1, 0);       // launch 3 = ncu slot
        k_spmm_upd<<<SPMM_BLOCKS, 256>>>(b, temps_vtoc, l * 2 + 0, 1);
    }

    k_out<<<2 * DENSE_BLOCKS, 256>>>(W1_o1, b1_o1, W2_o1,
                                     W1_o2, b1_o2, W2_o2, out);
}

// round 13
// speedup vs baseline: 1.1127x; 1.1127x over previous
#include <cuda_runtime.h>
#include <cuda_fp16.h>

#define NN   50000
#define NE   800000
#define EMB  64
#define FIN  32
#define SCALE_F 0.4251202479144762f

#define SCAN_BLK 1024
#define NBLK_SCAN 49            // ceil(50000/1024)

#define CHUNK 64
#define NCHUNK (NE / CHUNK)     // 12500
#define EDGE_BLOCKS ((NCHUNK + 7) / 8)   // 1563
#define UPD2_BLOCKS 782                  // grid-stride elementwise blocks

// ---------------- device scratch (static allocation; no cudaMalloc) ----------------
__device__ float g_cons[NN * EMB];
__device__ float g_var [NN * EMB];
__device__ float4 g_conv4[NN * 16];      // zero-init; re-zeroed by last-flusher after read
__device__ uint2 g_consh[NN * 16];       // half2 shadow of cons (gather operand)
__device__ uint2 g_uh   [NN * 16];       // half2 shadow of u    (gather operand)
__device__ int   g_rowptr[NN + 1];
__device__ int   g_cursor[NN];
__device__ int   g_hist [NN];            // zero at start; scan kernel re-zeroes after reading
__device__ int   g_rcnt [NN];            // zero-init; reset by last flusher each use
__device__ int   g_nexp [NN];            // 64-edge chunks overlapping each row
__device__ int2  g_epack[NE];            // CSR-ordered {dst, w-bits}
__device__ int   g_esrc [NE];            // CSR-ordered src (non-decreasing)
__device__ float g_part[512];
__device__ float g_inv_norm;
__device__ volatile int g_flag[64];      // lookback status: 0=invalid 1=agg 2=prefix
__device__ volatile int g_agg [64];
__device__ volatile int g_pref[64];

// ---------------- launch 0: histogram of src (warp-aggregated) + sumsq partials ----------------
__global__ void k_histsum(const int* __restrict__ ei, const float* __restrict__ ew) {
    int t = threadIdx.x;
    int lane = t & 31;
    if (blockIdx.x == 0 && t < 64) g_flag[t] = 0;
    int stride = gridDim.x * blockDim.x;
    float a = 0.0f;
    for (int e = blockIdx.x * blockDim.x + t; ; e += stride) {
        bool act = (e < NE);
        unsigned m = __ballot_sync(0xFFFFFFFFu, act);
        if (m == 0) break;
        if (act) {
            int s = ei[2 * e];
            unsigned grp = __match_any_sync(m, s);
            int leader = __ffs(grp) - 1;
            if (lane == leader) atomicAdd(&g_hist[s], __popc(grp));
            float w = ew[e];
            a = fmaf(w, w, a);
        }
    }
    __shared__ float red[256];
    red[t] = a;
    __syncthreads();
    for (int off = 128; off > 0; off >>= 1) {
        if (t < off) red[t] += red[t + off];
        __syncthreads();
    }
    if (t == 0) g_part[blockIdx.x] = red[0];
}

// ---------------- launch 1: single-pass decoupled-lookback scan -> rowptr/cursor, inv_norm ----------------
__global__ void __launch_bounds__(SCAN_BLK) k_scan() {
    __shared__ int s[SCAN_BLK];
    __shared__ int s_excl;
    int t = threadIdx.x, bid = blockIdx.x;
    int i = bid * SCAN_BLK + t;
    int val = 0;
    if (i < NN) {
        val = g_hist[i];
        g_hist[i] = 0;                      // restore invariant for next replay
    }
    s[t] = val;
    __syncthreads();
    for (int off = 1; off < SCAN_BLK; off <<= 1) {
        int v = (t >= off) ? s[t - off] : 0;
        __syncthreads();
        s[t] += v;
        __syncthreads();
    }
    int incl = s[t];
    int agg = s[SCAN_BLK - 1];
    if (t == 0) {
        if (bid == 0) {
            g_pref[0] = agg;
            __threadfence();
            g_flag[0] = 2;
            s_excl = 0;
        } else {
            g_agg[bid] = agg;
            __threadfence();
            g_flag[bid] = 1;
            int ex = 0;
            int p = bid - 1;
            while (true) {
                int f;
                while ((f = g_flag[p]) == 0) { }
                if (f == 2) { ex += g_pref[p]; break; }
                ex += g_agg[p];
                p--;
            }
            g_pref[bid] = ex + agg;
            __threadfence();
            g_flag[bid] = 2;
            s_excl = ex;
        }
    }
    __syncthreads();
    int r = incl - val + s_excl;
    if (i < NN) {
        g_rowptr[i] = r;
        g_cursor[i] = r;
    }
    if (bid == NBLK_SCAN - 1) {
        if (t == 0) g_rowptr[NN] = NE;
        __shared__ float fr[256];
        if (t < 256) fr[t] = g_part[t] + g_part[t + 256];
        __syncthreads();
        for (int off = 128; off > 0; off >>= 1) {
            if (t < off) fr[t] += fr[t + off];
            __syncthreads();
        }
        if (t == 0) g_inv_norm = 1.0f / sqrtf(fr[0]);
    }
}

// ---------------- pack 4 floats -> uint2 of half2 ----------------
__device__ __forceinline__ uint2 pack_h4(float a, float b, float c, float d) {
    __half2 lo = __floats2half2_rn(a, b);
    __half2 hi = __floats2half2_rn(c, d);
    uint2 r;
    r.x = *reinterpret_cast<unsigned*>(&lo);
    r.y = *reinterpret_cast<unsigned*>(&hi);
    return r;
}

// ---------------- register-tiled input GEMM: out = relu(x @ W + b), 64 rows/block ----------------
__device__ __forceinline__ void dense_in(const float* __restrict__ x, const float* __restrict__ W,
                                         const float* __restrict__ bias, float* __restrict__ out,
                                         uint2* __restrict__ outh, int row_base) {
    __shared__ float Ws[FIN][EMB];
    __shared__ float xsT[FIN][68];
    __shared__ float bs[EMB];
    int tid = threadIdx.x;
    for (int i = tid; i < FIN * EMB; i += 256) Ws[i >> 6][i & 63] = W[i];
    if (tid < EMB) bs[tid] = bias[tid];
    for (int i = tid; i < 64 * FIN; i += 256) {
        int r = i >> 5, k = i & 31;
        float v = 0.0f;
        if (row_base + r < NN) v = x[(row_base + r) * FIN + k];
        xsT[k][r] = v;
    }
    __syncthreads();
    int tx = tid & 15, ty = tid >> 4;
    int r0 = ty * 4, c0 = tx * 4;
    float acc[4][4];
#pragma unroll
    for (int i = 0; i < 4; i++) {
        acc[i][0] = bs[c0]; acc[i][1] = bs[c0 + 1]; acc[i][2] = bs[c0 + 2]; acc[i][3] = bs[c0 + 3];
    }
#pragma unroll
    for (int k = 0; k < FIN; k++) {
        float4 a = *reinterpret_cast<const float4*>(&xsT[k][r0]);
        float4 bq = *reinterpret_cast<const float4*>(&Ws[k][c0]);
        float av[4] = {a.x, a.y, a.z, a.w};
#pragma unroll
        for (int i = 0; i < 4; i++) {
            acc[i][0] = fmaf(av[i], bq.x, acc[i][0]);
            acc[i][1] = fmaf(av[i], bq.y, acc[i][1]);
            acc[i][2] = fmaf(av[i], bq.z, acc[i][2]);
            acc[i][3] = fmaf(av[i], bq.w, acc[i][3]);
        }
    }
#pragma unroll
    for (int i = 0; i < 4; i++) {
        int row = row_base + r0 + i;
        if (row < NN) {
            float4 o;
            o.x = fmaxf(acc[i][0], 0.0f); o.y = fmaxf(acc[i][1], 0.0f);
            o.z = fmaxf(acc[i][2], 0.0f); o.w = fmaxf(acc[i][3], 0.0f);
            *reinterpret_cast<float4*>(&out[row * EMB + c0]) = o;
            if (outh) outh[row * 16 + tx] = pack_h4(o.x, o.y, o.z, o.w);
        }
    }
}

#define DENSE_BLOCKS 782   // ceil(50000/64)
#define NEXP_BLOCKS 196    // ceil(50000/256)

// ---------------- launch 2: scatter (warp-aggregated) + input GEMMs + nexp precompute ----------------
__global__ void k_scatter_dense(const int* __restrict__ ei, const float* __restrict__ ew,
                                const float* __restrict__ xc, const float* __restrict__ Wc, const float* __restrict__ bc,
                                const float* __restrict__ xv, const float* __restrict__ Wv, const float* __restrict__ bv) {
    if (blockIdx.x < 512) {
        float inv = g_inv_norm;
        int lane = threadIdx.x & 31;
        int stride = 512 * blockDim.x;
        for (int e = blockIdx.x * blockDim.x + threadIdx.x; ; e += stride) {
            bool act = (e < NE);
            unsigned m = __ballot_sync(0xFFFFFFFFu, act);
            if (m == 0) break;
            if (act) {
                int s = ei[2 * e];
                int d = ei[2 * e + 1];
                unsigned grp = __match_any_sync(m, s);
                int leader = __ffs(grp) - 1;
                int rank = __popc(grp & ((1u << lane) - 1));
                int base = 0;
                if (lane == leader) base = atomicAdd(&g_cursor[s], __popc(grp));
                base = __shfl_sync(m, base, leader);
                int slot = base + rank;
                g_epack[slot] = make_int2(d, __float_as_int(ew[e] * inv));
                g_esrc[slot] = s;
            }
        }
    } else if (blockIdx.x < 512 + 2 * DENSE_BLOCKS) {
        int db = blockIdx.x - 512;
        if (db < DENSE_BLOCKS) dense_in(xc, Wc, bc, g_cons, g_consh, db * 64);
        else                   dense_in(xv, Wv, bv, g_var, 0, (db - DENSE_BLOCKS) * 64);
    } else {
        int i = (blockIdx.x - 512 - 2 * DENSE_BLOCKS) * 256 + threadIdx.x;
        if (i < NN) {
            int r0 = g_rowptr[i], r1 = g_rowptr[i + 1];
            g_nexp[i] = (r1 > r0) ? (((r1 - 1) >> 6) - (r0 >> 6) + 1) : 0;   // 64-edge chunks
        }
    }
}

// ---------------- flush: combine halves, 2 atomics/lane across 32 lanes, acq_rel counter ----------------
__device__ __forceinline__ void flush_and_count(int src, float4 acc, int lane, int q16, int h,
                                                const float* __restrict__ rhs,
                                                float t, int mode) {
    acc.x += __shfl_xor_sync(0xFFFFFFFFu, acc.x, 16);
    acc.y += __shfl_xor_sync(0xFFFFFFFFu, acc.y, 16);
    acc.z += __shfl_xor_sync(0xFFFFFFFFu, acc.z, 16);
    acc.w += __shfl_xor_sync(0xFFFFFFFFu, acc.w, 16);
    float* CONV = reinterpret_cast<float*>(g_conv4);
    {   // all 32 lanes: 2 atomics each (lower half x/y, upper half z/w)
        int o = src * 64 + q16 * 4 + h * 2;
        atomicAdd(&CONV[o],     h ? acc.z : acc.x);
        atomicAdd(&CONV[o + 1], h ? acc.w : acc.y);
    }
    __syncwarp();                               // orders lanes' conv adds before lane0's release
    int last = 0;
    if (lane == 0) {
        int old;
        asm volatile("atom.acq_rel.gpu.global.add.s32 %0, [%1], %2;"
                     : "=r"(old) : "l"(&g_rcnt[src]), "r"(1) : "memory");
        last = (old + 1 == g_nexp[src]);
    }
    last = __shfl_sync(0xFFFFFFFFu, last, 0);
    if (!last) return;
    __syncwarp();                               // propagate lane0's acquire to all lanes
    if (lane < 16) {
        int i = src * 16 + q16;
        float4 cv = __ldcg(&g_conv4[i]);
        float r = __ldg(&rhs[src]);
        if (mode == 0) {
            float4* V4 = reinterpret_cast<float4*>(g_var);
            float4 vo = V4[i], vn;
            vn.x = fmaxf((vo.x + t * (r - cv.x)) * SCALE_F, 0.0f);
            vn.y = fmaxf((vo.y + t * (r - cv.y)) * SCALE_F, 0.0f);
            vn.z = fmaxf((vo.z + t * (r - cv.z)) * SCALE_F, 0.0f);
            vn.w = fmaxf((vo.w + t * (r - cv.w)) * SCALE_F, 0.0f);
            V4[i] = vn;
            g_uh[i] = pack_h4(2.0f * vn.x - vo.x, 2.0f * vn.y - vo.y,
                              2.0f * vn.z - vo.z, 2.0f * vn.w - vo.w);
        } else {
            float4* C4 = reinterpret_cast<float4*>(g_cons);
            float4 co = C4[i], cn;
            cn.x = fmaxf(co.x - t * (r - cv.x), 0.0f);
            cn.y = fmaxf(co.y - t * (r - cv.y), 0.0f);
            cn.z = fmaxf(co.z - t * (r - cv.z), 0.0f);
            cn.w = fmaxf(co.w - t * (r - cv.w), 0.0f);
            C4[i] = cn;
            g_consh[i] = pack_h4(cn.x, cn.y, cn.z, cn.w);
        }
        g_conv4[i] = make_float4(0.0f, 0.0f, 0.0f, 0.0f);
    }
    __syncwarp();
    if (lane == 0) g_rcnt[src] = 0;
}

// ---------------- fp16 gather accumulate: 4 features per lane ----------------
__device__ __forceinline__ void gacc(const uint2* __restrict__ F16, int d, int q16,
                                     float w, float4& acc) {
    uint2 rv = __ldg(&F16[d * 16 + q16]);
    __half2 h0 = *reinterpret_cast<__half2*>(&rv.x);
    __half2 h1 = *reinterpret_cast<__half2*>(&rv.y);
    float2 f0 = __half22float2(h0);
    float2 f1 = __half22float2(h1);
    acc.x = fmaf(w, f0.x, acc.x);
    acc.y = fmaf(w, f0.y, acc.y);
    acc.z = fmaf(w, f1.x, acc.z);
    acc.w = fmaf(w, f1.y, acc.w);
}

// ---------------- fused SpMM + update: edge blocks, then grid-stride deg-0 elementwise (R8 grid) ----------------
__global__ void __launch_bounds__(256) k_spmm_upd(const float* __restrict__ rhs,
                                                  const float* __restrict__ temps,
                                                  int toff, int mode) {
    int tid = threadIdx.x;
    float t = __ldg(&temps[toff]);
    if (blockIdx.x < EDGE_BLOCKS) {
        int chunk = (blockIdx.x * 256 + tid) >> 5;
        if (chunk >= NCHUNK) return;
        const uint2* __restrict__ F16 = mode ? g_uh : g_consh;
        int lane = tid & 31;
        int h = lane >> 4;          // half 0: even edge of pair, half 1: odd
        int q16 = lane & 15;
        int base = chunk * CHUNK;

        // stage 64 edges in registers (coalesced)
        int2 p0 = g_epack[base + lane];
        int2 p1 = g_epack[base + 32 + lane];
        int  s0 = g_esrc [base + lane];
        int  s1 = g_esrc [base + 32 + lane];

        float4 acc = make_float4(0.0f, 0.0f, 0.0f, 0.0f);
        int cur = __shfl_sync(0xFFFFFFFFu, s0, 0);

        // ---- half A (edges 0..31 of chunk) ----
        int lastA = __shfl_sync(0xFFFFFFFFu, s0, 31);
        if (cur == lastA) {
#pragma unroll
            for (int j = 0; j < 32; j += 2) {
                int   d = __shfl_sync(0xFFFFFFFFu, p0.x, j + h);
                float w = __int_as_float(__shfl_sync(0xFFFFFFFFu, p0.y, j + h));
                gacc(F16, d, q16, w, acc);
            }
        } else {
            for (int j = 0; j < 32; j++) {
                int sj = __shfl_sync(0xFFFFFFFFu, s0, j);
                if (sj != cur) { flush_and_count(cur, acc, lane, q16, h, rhs, t, mode);
                                 acc = make_float4(0.0f, 0.0f, 0.0f, 0.0f); cur = sj; }
                int   d = __shfl_sync(0xFFFFFFFFu, p0.x, j);
                float w = __int_as_float(__shfl_sync(0xFFFFFFFFu, p0.y, j));
                if (h == 0) gacc(F16, d, q16, w, acc);
            }
        }

        // ---- half B (edges 32..63 of chunk) ----
        int firstB = __shfl_sync(0xFFFFFFFFu, s1, 0);
        int lastB  = __shfl_sync(0xFFFFFFFFu, s1, 31);
        if (firstB != cur) { flush_and_count(cur, acc, lane, q16, h, rhs, t, mode);
                             acc = make_float4(0.0f, 0.0f, 0.0f, 0.0f); cur = firstB; }
        if (firstB == lastB) {
#pragma unroll
            for (int j = 0; j < 32; j += 2) {
                int   d = __shfl_sync(0xFFFFFFFFu, p1.x, j + h);
                float w = __int_as_float(__shfl_sync(0xFFFFFFFFu, p1.y, j + h));
                gacc(F16, d, q16, w, acc);
            }
        } else {
            for (int j = 0; j < 32; j++) {
                int sj = __shfl_sync(0xFFFFFFFFu, s1, j);
                if (sj != cur) { flush_and_count(cur, acc, lane, q16, h, rhs, t, mode);
                                 acc = make_float4(0.0f, 0.0f, 0.0f, 0.0f); cur = sj; }
                int   d = __shfl_sync(0xFFFFFFFFu, p1.x, j);
                float w = __int_as_float(__shfl_sync(0xFFFFFFFFu, p1.y, j));
                if (h == 0) gacc(F16, d, q16, w, acc);
            }
        }
        flush_and_count(cur, acc, lane, q16, h, rhs, t, mode);
    } else {
        // grid-stride elementwise update for degree-0 rows (conv == 0)
        int stride = UPD2_BLOCKS * 256;
        for (int i = (blockIdx.x - EDGE_BLOCKS) * 256 + tid; i < NN * 16; i += stride) {
            int row = i >> 4;
            if (g_nexp[row] != 0) continue;
            float r = __ldg(&rhs[row]);
            if (mode == 0) {
                float4* V = reinterpret_cast<float4*>(g_var);
                float4 vo = V[i], vn;
                float add = t * r;
                vn.x = fmaxf((vo.x + add) * SCALE_F, 0.0f);
                vn.y = fmaxf((vo.y + add) * SCALE_F, 0.0f);
                vn.z = fmaxf((vo.z + add) * SCALE_F, 0.0f);
                vn.w = fmaxf((vo.w + add) * SCALE_F, 0.0f);
                V[i] = vn;
                g_uh[i] = pack_h4(2.0f * vn.x - vo.x, 2.0f * vn.y - vo.y,
                                  2.0f * vn.z - vo.z, 2.0f * vn.w - vo.w);
            } else {
                float4* C = reinterpret_cast<float4*>(g_cons);
                float4 co = C[i], cn;
                float sub = t * r;
                cn.x = fmaxf(co.x - sub, 0.0f);
                cn.y = fmaxf(co.y - sub, 0.0f);
                cn.z = fmaxf(co.z - sub, 0.0f);
                cn.w = fmaxf(co.w - sub, 0.0f);
                C[i] = cn;
                g_consh[i] = pack_h4(cn.x, cn.y, cn.z, cn.w);
            }
        }
    }
}

// ---------------- output heads (both in one launch): out = relu(x @ W1 + b1) @ W2 ----------------
__global__ void k_out(const float* __restrict__ W1a, const float* __restrict__ b1a, const float* __restrict__ W2a,
                      const float* __restrict__ W1b, const float* __restrict__ b1b, const float* __restrict__ W2b,
                      float* __restrict__ outbuf) {
    int which = (blockIdx.x >= DENSE_BLOCKS);
    const float* x  = which ? g_cons : g_var;
    const float* W1 = which ? W1b : W1a;
    const float* b1 = which ? b1b : b1a;
    const float* W2 = which ? W2b : W2a;
    float* out = outbuf + which * NN;
    int row_base = (blockIdx.x - which * DENSE_BLOCKS) * 64;

    __shared__ float W1s[EMB][EMB];
    __shared__ float xsT[EMB][68];
    __shared__ float b1s[EMB];
    __shared__ float W2s[EMB];
    int tid = threadIdx.x;
    for (int i = tid; i < EMB * EMB; i += 256) W1s[i >> 6][i & 63] = W1[i];
    if (tid < EMB) { b1s[tid] = b1[tid]; W2s[tid] = W2[tid]; }
    for (int i = tid; i < 64 * EMB; i += 256) {
        int r = i >> 6, k = i & 63;
        float v = 0.0f;
        if (row_base + r < NN) v = x[(row_base + r) * EMB + k];
        xsT[k][r] = v;
    }
    __syncthreads();
    int tx = tid & 15, ty = tid >> 4;
    int r0 = ty * 4, c0 = tx * 4;
    float acc[4][4];
#pragma unroll
    for (int i = 0; i < 4; i++) {
        acc[i][0] = b1s[c0]; acc[i][1] = b1s[c0 + 1]; acc[i][2] = b1s[c0 + 2]; acc[i][3] = b1s[c0 + 3];
    }
#pragma unroll
    for (int k = 0; k < EMB; k++) {
        float4 a = *reinterpret_cast<const float4*>(&xsT[k][r0]);
        float4 bq = *reinterpret_cast<const float4*>(&W1s[k][c0]);
        float av[4] = {a.x, a.y, a.z, a.w};
#pragma unroll
        for (int i = 0; i < 4; i++) {
            acc[i][0] = fmaf(av[i], bq.x, acc[i][0]);
            acc[i][1] = fmaf(av[i], bq.y, acc[i][1]);
            acc[i][2] = fmaf(av[i], bq.z, acc[i][2]);
            acc[i][3] = fmaf(av[i], bq.w, acc[i][3]);
        }
    }
    float4 w2 = *reinterpret_cast<const float4*>(&W2s[c0]);
#pragma unroll
    for (int i = 0; i < 4; i++) {
        float p = fmaxf(acc[i][0], 0.0f) * w2.x + fmaxf(acc[i][1], 0.0f) * w2.y
                + fmaxf(acc[i][2], 0.0f) * w2.z + fmaxf(acc[i][3], 0.0f) * w2.w;
        p += __shfl_down_sync(0xFFFFFFFFu, p, 8, 16);
        p += __shfl_down_sync(0xFFFFFFFFu, p, 4, 16);
        p += __shfl_down_sync(0xFFFFFFFFu, p, 2, 16);
        p += __shfl_down_sync(0xFFFFFFFFu, p, 1, 16);
        int row = row_base + r0 + i;
        if (tx == 0 && row < NN) out[row] = p;
    }
}

// ---------------- launch ----------------
extern "C" void kernel_launch(void* const* d_in, const int* in_sizes, int n_in,
                              void* d_out, int out_size) {
    const float* con_feat   = (const float*)d_in[0];
    const float* var_feat   = (const float*)d_in[1];
    const float* edge_w     = (const float*)d_in[2];
    const float* c          = (const float*)d_in[3];
    const float* b          = (const float*)d_in[4];
    const float* W_cons     = (const float*)d_in[5];
    const float* b_cons     = (const float*)d_in[6];
    const float* W_var      = (const float*)d_in[7];
    const float* b_var      = (const float*)d_in[8];
    const float* temps_ctov = (const float*)d_in[9];
    const float* temps_vtoc = (const float*)d_in[10];
    const float* W1_o1      = (const float*)d_in[11];
    const float* b1_o1      = (const float*)d_in[12];
    const float* W2_o1      = (const float*)d_in[13];
    const float* W1_o2      = (const float*)d_in[14];
    const float* b1_o2      = (const float*)d_in[15];
    const float* W2_o2      = (const float*)d_in[16];
    const int*   edge_index = (const int*)d_in[17];
    float* out = (float*)d_out;

    k_histsum<<<512, 256>>>(edge_index, edge_w);                             // launch 0
    k_scan   <<<NBLK_SCAN, SCAN_BLK>>>();                                    // launch 1
    k_scatter_dense<<<512 + 2 * DENSE_BLOCKS + NEXP_BLOCKS, 256>>>(          // launch 2
        edge_index, edge_w, con_feat, W_cons, b_cons, var_feat, W_var, b_var);

    for (int l = 0; l < 4; l++) {
        k_spmm_upd<<<EDGE_BLOCKS + UPD2_BLOCKS, 256>>>(c, temps_ctov, l * 2 + 1, 0);  // launch 3 = ncu slot
        k_spmm_upd<<<EDGE_BLOCKS + UPD2_BLOCKS, 256>>>(b, temps_vtoc, l * 2 + 0, 1);
    }

    k_out<<<2 * DENSE_BLOCKS, 256>>>(W1_o1, b1_o1, W2_o1,
                                     W1_o2, b1_o2, W2_o2, out);
}